// round 7
// baseline (speedup 1.0000x reference)
#include <cuda_runtime.h>
#include <math.h>

#define MAX_S 4096
__device__ float4 g_coeffs[2 * MAX_S];

#define BLOCK 256
#define GPT 2   // contiguous float4 groups per thread -> 8 samples

__global__ void spline_coeff_kernel(const float2* __restrict__ ctrl,
                                    const float2* __restrict__ joint,
                                    int S) {
    int s = blockIdx.x * blockDim.x + threadIdx.x;
    if (s >= S) return;
    float2 p0 = joint[s];
    float2 p3 = joint[s + 1];
    float2 p1 = ctrl[2 * s];
    float2 p2 = ctrl[2 * s + 1];

    float c1x = 3.0f * (p1.x - p0.x);
    float c1y = 3.0f * (p1.y - p0.y);
    float c2x = 3.0f * p0.x - 6.0f * p1.x + 3.0f * p2.x;
    float c2y = 3.0f * p0.y - 6.0f * p1.y + 3.0f * p2.y;
    float c3x = -p0.x + 3.0f * p1.x - 3.0f * p2.x + p3.x;
    float c3y = -p0.y + 3.0f * p1.y - 3.0f * p2.y + p3.y;

    g_coeffs[2 * s + 0] = make_float4(p0.x, p0.y, c1x, c1y);
    g_coeffs[2 * s + 1] = make_float4(c2x, c2y, c3x, c3y);
}

__device__ __forceinline__ void eval_one(const float4& a, const float4& b,
                                         float l, float& x, float& y) {
    float l2 = l * l;
    float l3 = l2 * l;
    x = fmaf(b.z, l3, fmaf(b.x, l2, fmaf(a.z, l, a.x)));
    y = fmaf(b.w, l3, fmaf(b.y, l2, fmaf(a.w, l, a.y)));
}

__global__ void __launch_bounds__(BLOCK)
spline_eval_kernel(const float4* __restrict__ t4,
                   float4* __restrict__ out4,
                   int n4, float Sf, int S) {
    const int tid = threadIdx.x;
    // thread handles two CONTIGUOUS float4 groups: warp spans 256 consecutive samples
    const int g0 = (blockIdx.x * BLOCK + tid) * GPT;
    const int g1 = g0 + 1;
    const bool v0 = g0 < n4;
    const bool v1 = g1 < n4;
    const int i0 = v0 ? g0 : (n4 - 1);   // clamp for warp-uniformity logic
    const int i1 = v1 ? g1 : (n4 - 1);

    // two independent loads (MLP=2)
    float4 tv0 = t4[i0];
    float4 tv1 = t4[i1];

    float ts[8] = {tv0.x, tv0.y, tv0.z, tv0.w, tv1.x, tv1.y, tv1.z, tv1.w};
    int   seg[8];
    float lt[8];
#pragma unroll
    for (int j = 0; j < 8; j++) {
        float tc = fminf(ts[j], 1.0f);
        float u = Sf * tc;
        int sg = (int)u;                 // u >= 0: trunc == floor
        float l = u - (float)sg;
        if (sg >= S) { sg = S - 1; l = 1.0f; }
        seg[j] = sg;
        lt[j] = l;
    }

    // warp-uniform? (sorted t: warp min = lane0 first sample, max = lane31 last)
    int lo = __shfl_sync(0xFFFFFFFFu, seg[0], 0);
    int hi = __shfl_sync(0xFFFFFFFFu, seg[7], 31);

    float rx[8], ry[8];
    if (lo == hi) {
        float4 a = __ldg(&g_coeffs[2 * lo + 0]);
        float4 b = __ldg(&g_coeffs[2 * lo + 1]);
#pragma unroll
        for (int j = 0; j < 8; j++)
            eval_one(a, b, lt[j], rx[j], ry[j]);
    } else {
        // boundary warp (~12%): per-thread uniform fast path inside
        if (seg[0] == seg[7]) {
            float4 a = __ldg(&g_coeffs[2 * seg[0] + 0]);
            float4 b = __ldg(&g_coeffs[2 * seg[0] + 1]);
#pragma unroll
            for (int j = 0; j < 8; j++)
                eval_one(a, b, lt[j], rx[j], ry[j]);
        } else {
#pragma unroll
            for (int j = 0; j < 8; j++) {
                float4 a = __ldg(&g_coeffs[2 * seg[j] + 0]);
                float4 b = __ldg(&g_coeffs[2 * seg[j] + 1]);
                eval_one(a, b, lt[j], rx[j], ry[j]);
            }
        }
    }

    // plain stores: let output stay dirty-resident in L2 across graph replays
    if (v0) {
        out4[2 * g0 + 0] = make_float4(rx[0], ry[0], rx[1], ry[1]);
        out4[2 * g0 + 1] = make_float4(rx[2], ry[2], rx[3], ry[3]);
    }
    if (v1) {
        out4[2 * g1 + 0] = make_float4(rx[4], ry[4], rx[5], ry[5]);
        out4[2 * g1 + 1] = make_float4(rx[6], ry[6], rx[7], ry[7]);
    }
}

// Scalar tail for n % 4 != 0 (not hit for N = 8388608)
__global__ void spline_eval_tail(const float* __restrict__ t,
                                 float2* __restrict__ out,
                                 int start, int n, float Sf, int S) {
    int i = start + blockIdx.x * blockDim.x + threadIdx.x;
    if (i >= n) return;
    float tc = fminf(t[i], 1.0f);
    float u = Sf * tc;
    int sg = (int)u;
    float l = u - (float)sg;
    if (sg >= S) { sg = S - 1; l = 1.0f; }
    float4 a = __ldg(&g_coeffs[2 * sg + 0]);
    float4 b = __ldg(&g_coeffs[2 * sg + 1]);
    float x, y;
    eval_one(a, b, l, x, y);
    out[i] = make_float2(x, y);
}

extern "C" void kernel_launch(void* const* d_in, const int* in_sizes, int n_in,
                              void* d_out, int out_size) {
    const float* t = (const float*)d_in[0];
    const float2* ctrl = (const float2*)d_in[1];
    const float2* joint = (const float2*)d_in[2];

    int n = in_sizes[0];
    int S = in_sizes[2] / 2 - 1;

    {
        int threads = 256;
        int blocks = (S + threads - 1) / threads;
        spline_coeff_kernel<<<blocks, threads>>>(ctrl, joint, S);
    }

    int n4 = n / 4;
    if (n4 > 0) {
        int perBlock = BLOCK * GPT;
        int blocks = (n4 + perBlock - 1) / perBlock;
        spline_eval_kernel<<<blocks, BLOCK>>>((const float4*)t, (float4*)d_out,
                                              n4, (float)S, S);
    }
    int rem = n - n4 * 4;
    if (rem > 0) {
        spline_eval_tail<<<1, 128>>>(t, (float2*)d_out, n4 * 4, n, (float)S, S);
    }
}

// round 8
// speedup vs baseline: 1.1514x; 1.1514x over previous
#include <cuda_runtime.h>
#include <math.h>

#define MAX_S 4096
__device__ float4 g_coeffs[2 * MAX_S];

#define BLOCK 256

__global__ void spline_coeff_kernel(const float2* __restrict__ ctrl,
                                    const float2* __restrict__ joint,
                                    int S) {
    int s = blockIdx.x * blockDim.x + threadIdx.x;
    if (s >= S) return;
    float2 p0 = joint[s];
    float2 p3 = joint[s + 1];
    float2 p1 = ctrl[2 * s];
    float2 p2 = ctrl[2 * s + 1];

    float c1x = 3.0f * (p1.x - p0.x);
    float c1y = 3.0f * (p1.y - p0.y);
    float c2x = 3.0f * p0.x - 6.0f * p1.x + 3.0f * p2.x;
    float c2y = 3.0f * p0.y - 6.0f * p1.y + 3.0f * p2.y;
    float c3x = -p0.x + 3.0f * p1.x - 3.0f * p2.x + p3.x;
    float c3y = -p0.y + 3.0f * p1.y - 3.0f * p2.y + p3.y;

    g_coeffs[2 * s + 0] = make_float4(p0.x, p0.y, c1x, c1y);
    g_coeffs[2 * s + 1] = make_float4(c2x, c2y, c3x, c3y);
}

__device__ __forceinline__ void eval_one(const float4& a, const float4& b,
                                         float l, float& x, float& y) {
    float l2 = l * l;
    float l3 = l2 * l;
    x = fmaf(b.z, l3, fmaf(b.x, l2, fmaf(a.z, l, a.x)));
    y = fmaf(b.w, l3, fmaf(b.y, l2, fmaf(a.w, l, a.y)));
}

// Core: one float4 t-group per thread. Assumes i < n4 (caller guarantees).
__device__ __forceinline__ void eval_group(const float4* __restrict__ t4,
                                           float4* __restrict__ out4,
                                           int i, float Sf, int S) {
    float4 tv = t4[i];
    float u[4];
    u[0] = Sf * fminf(tv.x, 1.0f);
    u[1] = Sf * fminf(tv.y, 1.0f);
    u[2] = Sf * fminf(tv.z, 1.0f);
    u[3] = Sf * fminf(tv.w, 1.0f);

    // Warp-edge uniformity test only (t sorted): lane0 first vs lane31 last.
    int sg_first = (int)u[0];
    int sg_last  = (int)u[3];
    int lo = __shfl_sync(0xFFFFFFFFu, sg_first, 0);
    int hi = __shfl_sync(0xFFFFFFFFu, sg_last, 31);

    float rx[4], ry[4];
    if (lo == hi && lo < S) {
        // whole warp in one segment: derive lt directly, 2 broadcast loads
        float4 a = __ldg(&g_coeffs[2 * lo + 0]);
        float4 b = __ldg(&g_coeffs[2 * lo + 1]);
        float sgf = (float)lo;
#pragma unroll
        for (int j = 0; j < 4; j++)
            eval_one(a, b, u[j] - sgf, rx[j], ry[j]);
    } else {
        // boundary warp: per-sample seg/lt with full clamping
#pragma unroll
        for (int j = 0; j < 4; j++) {
            int sg = (int)u[j];
            float l = u[j] - (float)sg;
            if (sg >= S) { sg = S - 1; l = 1.0f; }
            float4 a = __ldg(&g_coeffs[2 * sg + 0]);
            float4 b = __ldg(&g_coeffs[2 * sg + 1]);
            eval_one(a, b, l, rx[j], ry[j]);
        }
    }

    out4[2 * i + 0] = make_float4(rx[0], ry[0], rx[1], ry[1]);
    out4[2 * i + 1] = make_float4(rx[2], ry[2], rx[3], ry[3]);
}

// Unguarded: grid * BLOCK == n4 exactly.
__global__ void __launch_bounds__(BLOCK)
spline_eval_exact(const float4* __restrict__ t4, float4* __restrict__ out4,
                  float Sf, int S) {
    eval_group(t4, out4, blockIdx.x * BLOCK + threadIdx.x, Sf, S);
}

// Guarded fallback for non-divisible n4.
__global__ void __launch_bounds__(BLOCK)
spline_eval_guard(const float4* __restrict__ t4, float4* __restrict__ out4,
                  int n4, float Sf, int S) {
    int i = blockIdx.x * BLOCK + threadIdx.x;
    if (i < n4) eval_group(t4, out4, i, Sf, S);
}

// Scalar tail for n % 4 != 0 (not hit for N = 8388608)
__global__ void spline_eval_tail(const float* __restrict__ t,
                                 float2* __restrict__ out,
                                 int start, int n, float Sf, int S) {
    int i = start + blockIdx.x * blockDim.x + threadIdx.x;
    if (i >= n) return;
    float u = Sf * fminf(t[i], 1.0f);
    int sg = (int)u;
    float l = u - (float)sg;
    if (sg >= S) { sg = S - 1; l = 1.0f; }
    float4 a = __ldg(&g_coeffs[2 * sg + 0]);
    float4 b = __ldg(&g_coeffs[2 * sg + 1]);
    float x, y;
    eval_one(a, b, l, x, y);
    out[i] = make_float2(x, y);
}

extern "C" void kernel_launch(void* const* d_in, const int* in_sizes, int n_in,
                              void* d_out, int out_size) {
    const float* t = (const float*)d_in[0];
    const float2* ctrl = (const float2*)d_in[1];
    const float2* joint = (const float2*)d_in[2];

    int n = in_sizes[0];
    int S = in_sizes[2] / 2 - 1;

    {
        int threads = 256;
        int blocks = (S + threads - 1) / threads;
        spline_coeff_kernel<<<blocks, threads>>>(ctrl, joint, S);
    }

    int n4 = n / 4;
    if (n4 > 0) {
        if (n4 % BLOCK == 0) {
            spline_eval_exact<<<n4 / BLOCK, BLOCK>>>((const float4*)t,
                                                     (float4*)d_out, (float)S, S);
        } else {
            spline_eval_guard<<<(n4 + BLOCK - 1) / BLOCK, BLOCK>>>(
                (const float4*)t, (float4*)d_out, n4, (float)S, S);
        }
    }
    int rem = n - n4 * 4;
    if (rem > 0) {
        spline_eval_tail<<<1, 128>>>(t, (float2*)d_out, n4 * 4, n, (float)S, S);
    }
}

// round 9
// speedup vs baseline: 1.2058x; 1.0473x over previous
#include <cuda_runtime.h>
#include <math.h>
#include <cstdint>

#define MAX_S 4096
__device__ float4 g_coeffs[2 * MAX_S];

#define BLOCK 256
#define OUT_TILE_BYTES (BLOCK * 32)   // 2 float4 per thread = 8192 B per block

__global__ void spline_coeff_kernel(const float2* __restrict__ ctrl,
                                    const float2* __restrict__ joint,
                                    int S) {
    int s = blockIdx.x * blockDim.x + threadIdx.x;
    if (s >= S) return;
    float2 p0 = joint[s];
    float2 p3 = joint[s + 1];
    float2 p1 = ctrl[2 * s];
    float2 p2 = ctrl[2 * s + 1];

    float c1x = 3.0f * (p1.x - p0.x);
    float c1y = 3.0f * (p1.y - p0.y);
    float c2x = 3.0f * p0.x - 6.0f * p1.x + 3.0f * p2.x;
    float c2y = 3.0f * p0.y - 6.0f * p1.y + 3.0f * p2.y;
    float c3x = -p0.x + 3.0f * p1.x - 3.0f * p2.x + p3.x;
    float c3y = -p0.y + 3.0f * p1.y - 3.0f * p2.y + p3.y;

    g_coeffs[2 * s + 0] = make_float4(p0.x, p0.y, c1x, c1y);
    g_coeffs[2 * s + 1] = make_float4(c2x, c2y, c3x, c3y);
}

__device__ __forceinline__ void eval_one(const float4& a, const float4& b,
                                         float l, float& x, float& y) {
    float l2 = l * l;
    float l3 = l2 * l;
    x = fmaf(b.z, l3, fmaf(b.x, l2, fmaf(a.z, l, a.x)));
    y = fmaf(b.w, l3, fmaf(b.y, l2, fmaf(a.w, l, a.y)));
}

__device__ __forceinline__ void eval4(const float4& tv, float Sf, int S,
                                      float* rx, float* ry) {
    float u[4];
    u[0] = Sf * fminf(tv.x, 1.0f);
    u[1] = Sf * fminf(tv.y, 1.0f);
    u[2] = Sf * fminf(tv.z, 1.0f);
    u[3] = Sf * fminf(tv.w, 1.0f);

    int lo = __shfl_sync(0xFFFFFFFFu, (int)u[0], 0);
    int hi = __shfl_sync(0xFFFFFFFFu, (int)u[3], 31);

    if (lo == hi && lo < S) {
        float4 a = __ldg(&g_coeffs[2 * lo + 0]);
        float4 b = __ldg(&g_coeffs[2 * lo + 1]);
        float sgf = (float)lo;
#pragma unroll
        for (int j = 0; j < 4; j++)
            eval_one(a, b, u[j] - sgf, rx[j], ry[j]);
    } else {
#pragma unroll
        for (int j = 0; j < 4; j++) {
            int sg = (int)u[j];
            float l = u[j] - (float)sg;
            if (sg >= S) { sg = S - 1; l = 1.0f; }
            float4 a = __ldg(&g_coeffs[2 * sg + 0]);
            float4 b = __ldg(&g_coeffs[2 * sg + 1]);
            eval_one(a, b, l, rx[j], ry[j]);
        }
    }
}

// Unguarded: grid * BLOCK == n4 exactly. Output staged in smem, emitted as
// one 8 KB TMA bulk store per block (full-line writes, no per-thread STG).
__global__ void __launch_bounds__(BLOCK)
spline_eval_bulkout(const float4* __restrict__ t4, float4* __restrict__ out4,
                    float Sf, int S) {
    __shared__ alignas(128) float4 s_out[2 * BLOCK];

    const int tid = threadIdx.x;
    const int i = blockIdx.x * BLOCK + tid;

    float4 tv = t4[i];
    float rx[4], ry[4];
    eval4(tv, Sf, S, rx, ry);

    // mirror the global layout inside the block tile
    s_out[2 * tid + 0] = make_float4(rx[0], ry[0], rx[1], ry[1]);
    s_out[2 * tid + 1] = make_float4(rx[2], ry[2], rx[3], ry[3]);

    __syncthreads();

    if (tid == 0) {
        uint32_t src = (uint32_t)__cvta_generic_to_shared(&s_out[0]);
        float4* dst = out4 + 2 * (size_t)blockIdx.x * BLOCK;
        asm volatile("fence.proxy.async.shared::cta;" ::: "memory");
        asm volatile("cp.async.bulk.global.shared::cta.bulk_group [%0], [%1], %2;"
                     :: "l"(dst), "r"(src), "n"(OUT_TILE_BYTES) : "memory");
        asm volatile("cp.async.bulk.commit_group;" ::: "memory");
        asm volatile("cp.async.bulk.wait_group 0;" ::: "memory");
    }
}

// Guarded fallback for non-divisible n4 (plain stores).
__global__ void __launch_bounds__(BLOCK)
spline_eval_guard(const float4* __restrict__ t4, float4* __restrict__ out4,
                  int n4, float Sf, int S) {
    int i = blockIdx.x * BLOCK + threadIdx.x;
    bool valid = i < n4;
    int ii = valid ? i : (n4 - 1);
    float4 tv = t4[ii];
    float rx[4], ry[4];
    eval4(tv, Sf, S, rx, ry);
    if (valid) {
        out4[2 * i + 0] = make_float4(rx[0], ry[0], rx[1], ry[1]);
        out4[2 * i + 1] = make_float4(rx[2], ry[2], rx[3], ry[3]);
    }
}

// Scalar tail for n % 4 != 0 (not hit for N = 8388608)
__global__ void spline_eval_tail(const float* __restrict__ t,
                                 float2* __restrict__ out,
                                 int start, int n, float Sf, int S) {
    int i = start + blockIdx.x * blockDim.x + threadIdx.x;
    if (i >= n) return;
    float u = Sf * fminf(t[i], 1.0f);
    int sg = (int)u;
    float l = u - (float)sg;
    if (sg >= S) { sg = S - 1; l = 1.0f; }
    float4 a = __ldg(&g_coeffs[2 * sg + 0]);
    float4 b = __ldg(&g_coeffs[2 * sg + 1]);
    float x, y;
    eval_one(a, b, l, x, y);
    out[i] = make_float2(x, y);
}

extern "C" void kernel_launch(void* const* d_in, const int* in_sizes, int n_in,
                              void* d_out, int out_size) {
    const float* t = (const float*)d_in[0];
    const float2* ctrl = (const float2*)d_in[1];
    const float2* joint = (const float2*)d_in[2];

    int n = in_sizes[0];
    int S = in_sizes[2] / 2 - 1;

    {
        int threads = 256;
        int blocks = (S + threads - 1) / threads;
        spline_coeff_kernel<<<blocks, threads>>>(ctrl, joint, S);
    }

    int n4 = n / 4;
    if (n4 > 0) {
        if (n4 % BLOCK == 0) {
            spline_eval_bulkout<<<n4 / BLOCK, BLOCK>>>((const float4*)t,
                                                       (float4*)d_out, (float)S, S);
        } else {
            spline_eval_guard<<<(n4 + BLOCK - 1) / BLOCK, BLOCK>>>(
                (const float4*)t, (float4*)d_out, n4, (float)S, S);
        }
    }
    int rem = n - n4 * 4;
    if (rem > 0) {
        spline_eval_tail<<<1, 128>>>(t, (float2*)d_out, n4 * 4, n, (float)S, S);
    }
}